// round 1
// baseline (speedup 1.0000x reference)
#include <cuda_runtime.h>
#include <math.h>

// ---------------------------------------------------------------------------
// Problem constants
// ---------------------------------------------------------------------------
#define BATCH   8
#define SEQL    2048
#define D_IN    512
#define DMODEL  1024
#define NROW    (BATCH * SEQL)          // 16384
#define LN_EPS  1e-5f

static const long long SZ_MAT   = (long long)NROW * DMODEL;          // 16,777,216
static const long long SZ_SCORE = (long long)BATCH * SEQL * SEQL;    // 33,554,432

// scratch arena: X, Q, K, V, Z, H, SK, SCORE, T
__device__ float g_scratch[7 * 16777216LL + 33554432LL + 16384LL];

#define O_X     (0LL)
#define O_Q     (1LL * 16777216LL)
#define O_K     (2LL * 16777216LL)
#define O_V     (3LL * 16777216LL)
#define O_Z     (4LL * 16777216LL)
#define O_H     (5LL * 16777216LL)
#define O_SK    (6LL * 16777216LL)
#define O_SCORE (7LL * 16777216LL)
#define O_T     (7LL * 16777216LL + 33554432LL)

// ---------------------------------------------------------------------------
// Generic fp32 GEMM: C[m,n] = alpha * sum_k A[m,k] * B(n,k)  (+bias +posenc)
//   BNK=true : B stored [N,K] row-major (weights, or K for Q*K^T)
//   BNK=false: B stored [K,N] row-major (V for score*V)
// Tiles: 128x128x8, 256 threads, 8x8 per thread, register prefetch.
// All dims must be multiples of the tile (true for every call here).
// ---------------------------------------------------------------------------
#define BM 128
#define BN 128
#define BK 8

template <bool BNK>
__global__ __launch_bounds__(256, 2)
void gemm_kernel(const float* __restrict__ A, const float* __restrict__ Bm,
                 float* __restrict__ C, int M, int N, int K,
                 long long sA, long long sB, long long sC,
                 float alpha,
                 const float* __restrict__ bias,
                 const float* __restrict__ posenc)
{
    __shared__ __align__(16) float As[BK][BM];
    __shared__ __align__(16) float Bs[BK][BN];

    const int tid = threadIdx.x;
    const int bz  = blockIdx.z;
    A  += bz * sA;
    Bm += bz * sB;
    C  += bz * sC;

    const int m0 = blockIdx.y * BM;
    const int n0 = blockIdx.x * BN;

    // A tile loader: thread loads float4 at row (tid>>1), k-offset (tid&1)*4
    const int ar = tid >> 1;
    const int ak = (tid & 1) * 4;
    const float* Ag = A + (long long)(m0 + ar) * K + ak;

    // B tile loader
    int br, bkk;
    const float* Bg;
    if (BNK) {
        br  = tid >> 1;
        bkk = (tid & 1) * 4;
        Bg  = Bm + (long long)(n0 + br) * K + bkk;
    } else {
        br  = tid >> 5;          // k row 0..7
        bkk = (tid & 31) * 4;    // n offset
        Bg  = Bm + (long long)br * N + n0 + bkk;
    }

    const int tx = tid & 15;
    const int ty = tid >> 4;

    float acc[8][8];
#pragma unroll
    for (int i = 0; i < 8; i++)
#pragma unroll
        for (int j = 0; j < 8; j++) acc[i][j] = 0.0f;

    // initial prefetch
    float4 ra = *(const float4*)(Ag);
    float4 rb;
    if (BNK) rb = *(const float4*)(Bg);
    else     rb = *(const float4*)(Bg);

    for (int k0 = 0; k0 < K; k0 += BK) {
        // commit prefetched regs to smem
        As[ak + 0][ar] = ra.x;
        As[ak + 1][ar] = ra.y;
        As[ak + 2][ar] = ra.z;
        As[ak + 3][ar] = ra.w;
        if (BNK) {
            Bs[bkk + 0][br] = rb.x;
            Bs[bkk + 1][br] = rb.y;
            Bs[bkk + 2][br] = rb.z;
            Bs[bkk + 3][br] = rb.w;
        } else {
            *(float4*)&Bs[br][bkk] = rb;
        }
        __syncthreads();

        // prefetch next tile (overlaps with compute below)
        if (k0 + BK < K) {
            ra = *(const float4*)(Ag + (k0 + BK));
            if (BNK) rb = *(const float4*)(Bg + (k0 + BK));
            else     rb = *(const float4*)(Bg + (long long)(k0 + BK) * N);
        }

#pragma unroll
        for (int kk = 0; kk < BK; kk++) {
            float a[8], b[8];
            *(float4*)&a[0] = *(const float4*)&As[kk][ty * 8];
            *(float4*)&a[4] = *(const float4*)&As[kk][ty * 8 + 4];
            *(float4*)&b[0] = *(const float4*)&Bs[kk][tx * 8];
            *(float4*)&b[4] = *(const float4*)&Bs[kk][tx * 8 + 4];
#pragma unroll
            for (int i = 0; i < 8; i++)
#pragma unroll
                for (int j = 0; j < 8; j++)
                    acc[i][j] += a[i] * b[j];
        }
        __syncthreads();
    }

    // epilogue
    const int mbase = m0 + ty * 8;
    const int nbase = n0 + tx * 8;
#pragma unroll
    for (int i = 0; i < 8; i++) {
        const int m = mbase + i;
        float* Crow = C + (long long)m * N + nbase;
        const float* pe = posenc ? (posenc + (long long)(m & (SEQL - 1)) * N + nbase)
                                 : (const float*)0;
#pragma unroll
        for (int j = 0; j < 8; j++) {
            float v = acc[i][j] * alpha;
            if (bias) v += bias[nbase + j];
            if (pe)   v += pe[j];
            Crow[j] = v;
        }
    }
}

// ---------------------------------------------------------------------------
// Row softmax, in place. Row length must be 2048, blockDim 256.
// ---------------------------------------------------------------------------
__global__ void softmax_rows(float* __restrict__ S)
{
    float* row = S + (long long)blockIdx.x * 2048;
    const int tid = threadIdx.x;
    __shared__ float red[256];

    float v[8];
    float mx = -1e30f;
#pragma unroll
    for (int i = 0; i < 8; i++) {
        v[i] = row[tid + i * 256];
        mx = fmaxf(mx, v[i]);
    }
    red[tid] = mx; __syncthreads();
    for (int s = 128; s > 0; s >>= 1) {
        if (tid < s) red[tid] = fmaxf(red[tid], red[tid + s]);
        __syncthreads();
    }
    mx = red[0]; __syncthreads();

    float sum = 0.0f;
#pragma unroll
    for (int i = 0; i < 8; i++) {
        v[i] = __expf(v[i] - mx);
        sum += v[i];
    }
    red[tid] = sum; __syncthreads();
    for (int s = 128; s > 0; s >>= 1) {
        if (tid < s) red[tid] += red[tid + s];
        __syncthreads();
    }
    const float inv = 1.0f / red[0];
#pragma unroll
    for (int i = 0; i < 8; i++)
        row[tid + i * 256] = v[i] * inv;
}

// ---------------------------------------------------------------------------
// h = x + z ; H = LayerNorm(h) * g + b        one block per row, 256 threads
// ---------------------------------------------------------------------------
__global__ void add_ln_kernel(const float* __restrict__ X, const float* __restrict__ Z,
                              const float* __restrict__ g, const float* __restrict__ b,
                              float* __restrict__ H)
{
    const long long r = blockIdx.x;
    const int tid = threadIdx.x;
    const float* xr = X + r * DMODEL;
    const float* zr = Z + r * DMODEL;
    __shared__ float red[256];

    float h[4];
    float sum = 0.0f;
#pragma unroll
    for (int i = 0; i < 4; i++) {
        h[i] = xr[tid + i * 256] + zr[tid + i * 256];
        sum += h[i];
    }
    red[tid] = sum; __syncthreads();
    for (int s = 128; s > 0; s >>= 1) {
        if (tid < s) red[tid] += red[tid + s];
        __syncthreads();
    }
    const float mean = red[0] * (1.0f / DMODEL);
    __syncthreads();

    float vs = 0.0f;
#pragma unroll
    for (int i = 0; i < 4; i++) {
        const float d = h[i] - mean;
        vs += d * d;
    }
    red[tid] = vs; __syncthreads();
    for (int s = 128; s > 0; s >>= 1) {
        if (tid < s) red[tid] += red[tid + s];
        __syncthreads();
    }
    const float inv = rsqrtf(red[0] * (1.0f / DMODEL) + LN_EPS);

    float* Hr = H + r * DMODEL;
#pragma unroll
    for (int i = 0; i < 4; i++) {
        const int c = tid + i * 256;
        Hr[c] = (h[i] - mean) * inv * g[c] + b[c];
    }
}

// ---------------------------------------------------------------------------
// t[r] = sum_o tanh(SK[r,o]) * q[o]           one block per row
// ---------------------------------------------------------------------------
__global__ void softkey_reduce(const float* __restrict__ SK, const float* __restrict__ q,
                               float* __restrict__ t)
{
    const long long r = blockIdx.x;
    const int tid = threadIdx.x;
    __shared__ float red[256];

    float s = 0.0f;
#pragma unroll
    for (int i = 0; i < 4; i++) {
        const int c = tid + i * 256;
        s += tanhf(SK[r * DMODEL + c]) * q[c];
    }
    red[tid] = s; __syncthreads();
    for (int k = 128; k > 0; k >>= 1) {
        if (tid < k) red[tid] += red[tid + k];
        __syncthreads();
    }
    if (tid == 0) t[r] = red[0];
}

// ---------------------------------------------------------------------------
// out[b,o] = sum_s w[b,s] * H[b,s,o]   grid (4, 8), 256 threads; deterministic
// ---------------------------------------------------------------------------
__global__ void final_out(const float* __restrict__ H, const float* __restrict__ w,
                          float* __restrict__ out)
{
    const int b = blockIdx.y;
    const int o = blockIdx.x * 256 + threadIdx.x;
    const float* Hb = H + (long long)b * SEQL * DMODEL;
    const float* wb = w + (long long)b * SEQL;

    float a0 = 0.0f, a1 = 0.0f, a2 = 0.0f, a3 = 0.0f;
    for (int s = 0; s < SEQL; s += 4) {
        a0 += wb[s + 0] * Hb[(long long)(s + 0) * DMODEL + o];
        a1 += wb[s + 1] * Hb[(long long)(s + 1) * DMODEL + o];
        a2 += wb[s + 2] * Hb[(long long)(s + 2) * DMODEL + o];
        a3 += wb[s + 3] * Hb[(long long)(s + 3) * DMODEL + o];
    }
    out[b * DMODEL + o] = (a0 + a1) + (a2 + a3);
}

// ---------------------------------------------------------------------------
// Launch
// ---------------------------------------------------------------------------
extern "C" void kernel_launch(void* const* d_in, const int* in_sizes, int n_in,
                              void* d_out, int out_size)
{
    const float* inputs  = (const float*)d_in[0];
    const float* embed_w = (const float*)d_in[1];
    const float* embed_b = (const float*)d_in[2];
    const float* wq_w    = (const float*)d_in[3];
    const float* wq_b    = (const float*)d_in[4];
    const float* wk_w    = (const float*)d_in[5];
    const float* wk_b    = (const float*)d_in[6];
    const float* wv_w    = (const float*)d_in[7];
    const float* wv_b    = (const float*)d_in[8];
    const float* ln_g    = (const float*)d_in[9];
    const float* ln_b    = (const float*)d_in[10];
    const float* skw     = (const float*)d_in[11];
    const float* sq      = (const float*)d_in[12];
    const float* pos     = (const float*)d_in[13];
    float* out = (float*)d_out;

    float* base = 0;
    cudaGetSymbolAddress((void**)&base, g_scratch);
    float* X  = base + O_X;
    float* Q  = base + O_Q;
    float* K  = base + O_K;
    float* V  = base + O_V;
    float* Z  = base + O_Z;
    float* H  = base + O_H;
    float* SK = base + O_SK;
    float* SC = base + O_SCORE;
    float* T  = base + O_T;

    // 1) embed: X = inputs @ embed_w^T + embed_b + pos_enc
    gemm_kernel<true><<<dim3(DMODEL / BN, NROW / BM, 1), 256>>>(
        inputs, embed_w, X, NROW, DMODEL, D_IN, 0, 0, 0, 1.0f, embed_b, pos);

    // 2) Q, K, V
    gemm_kernel<true><<<dim3(DMODEL / BN, NROW / BM, 1), 256>>>(
        X, wq_w, Q, NROW, DMODEL, DMODEL, 0, 0, 0, 1.0f, wq_b, 0);
    gemm_kernel<true><<<dim3(DMODEL / BN, NROW / BM, 1), 256>>>(
        X, wk_w, K, NROW, DMODEL, DMODEL, 0, 0, 0, 1.0f, wk_b, 0);
    gemm_kernel<true><<<dim3(DMODEL / BN, NROW / BM, 1), 256>>>(
        X, wv_w, V, NROW, DMODEL, DMODEL, 0, 0, 0, 1.0f, wv_b, 0);

    // 3) scores = Q @ K^T / 32   (batched over 8)
    gemm_kernel<true><<<dim3(SEQL / BN, SEQL / BM, BATCH), 256>>>(
        Q, K, SC, SEQL, SEQL, DMODEL,
        (long long)SEQL * DMODEL, (long long)SEQL * DMODEL, (long long)SEQL * SEQL,
        1.0f / 32.0f, 0, 0);

    // 4) softmax over rows
    softmax_rows<<<NROW, 256>>>(SC);

    // 5) Z = score @ V    (batched, B is [K,N])
    gemm_kernel<false><<<dim3(DMODEL / BN, SEQL / BM, BATCH), 256>>>(
        SC, V, Z, SEQL, DMODEL, SEQL,
        (long long)SEQL * SEQL, (long long)SEQL * DMODEL, (long long)SEQL * DMODEL,
        1.0f, 0, 0);

    // 6) H = LN(X + Z) * g + b
    add_ln_kernel<<<NROW, 256>>>(X, Z, ln_g, ln_b, H);

    // 7) SK = H @ soft_key_w^T   (tanh applied in reduce)
    gemm_kernel<true><<<dim3(DMODEL / BN, NROW / BM, 1), 256>>>(
        H, skw, SK, NROW, DMODEL, DMODEL, 0, 0, 0, 1.0f, 0, 0);

    // 8) t[b,s] = sum_o tanh(SK) * soft_query[o]; softmax over s per batch
    softkey_reduce<<<NROW, 256>>>(SK, sq, T);
    softmax_rows<<<BATCH, 256>>>(T);

    // 9) out[b,o] = sum_s w[b,s] * H[b,s,o]
    final_out<<<dim3(DMODEL / 256, BATCH), 256>>>(H, T, out);
}

// round 4
// speedup vs baseline: 2.3192x; 2.3192x over previous
#include <cuda_runtime.h>
#include <cstdint>
#include <math.h>

// ---------------------------------------------------------------------------
// Problem constants
// ---------------------------------------------------------------------------
#define BATCH   8
#define SEQL    2048
#define D_IN    512
#define DMODEL  1024
#define NROW    (BATCH * SEQL)          // 16384
#define LN_EPS  1e-5f

// scratch arena: X, Q, K, V, Z, H, SK, SCORE, T
__device__ float g_scratch[7 * 16777216LL + 33554432LL + 16384LL];

#define O_X     (0LL)
#define O_Q     (1LL * 16777216LL)
#define O_K     (2LL * 16777216LL)
#define O_V     (3LL * 16777216LL)
#define O_Z     (4LL * 16777216LL)
#define O_H     (5LL * 16777216LL)
#define O_SK    (6LL * 16777216LL)
#define O_SCORE (7LL * 16777216LL)
#define O_T     (7LL * 16777216LL + 33554432LL)

// ---------------------------------------------------------------------------
// PTX helpers (baseline sm_80+ features only — harness targets plain sm_103)
// ---------------------------------------------------------------------------
__device__ __forceinline__ uint32_t smem_u32(const void* p) {
    uint32_t a;
    asm("{ .reg .u64 t; cvta.to.shared.u64 t, %1; cvt.u32.u64 %0, t; }"
        : "=r"(a) : "l"(p));
    return a;
}

__device__ __forceinline__ void cp_async16(uint32_t dst, const void* src) {
    asm volatile("cp.async.cg.shared.global [%0], [%1], 16;" :: "r"(dst), "l"(src));
}
#define CP_COMMIT() asm volatile("cp.async.commit_group;" ::: "memory")
#define CP_WAIT1()  asm volatile("cp.async.wait_group 1;"  ::: "memory")

// split x0,x1 (fp32) into packed bf16x2 hi and lo parts:
//   x = hi + lo (+O(2^-17)) ; reg low half = x0, high half = x1
__device__ __forceinline__ void split_pack(float x0, float x1,
                                           uint32_t& hi, uint32_t& lo) {
    asm("cvt.rn.bf16x2.f32 %0, %1, %2;" : "=r"(hi) : "f"(x1), "f"(x0));
    const float h0 = __uint_as_float(hi << 16);
    const float h1 = __uint_as_float(hi & 0xFFFF0000u);
    const float l0 = x0 - h0;
    const float l1 = x1 - h1;
    asm("cvt.rn.bf16x2.f32 %0, %1, %2;" : "=r"(lo) : "f"(l1), "f"(l0));
}

// D += A*B  (m16n8k16 bf16, fp32 accum)
__device__ __forceinline__ void mma_bf16(float* d, const uint32_t* a, const uint32_t* b) {
    asm volatile(
        "mma.sync.aligned.m16n8k16.row.col.f32.bf16.bf16.f32 "
        "{%0,%1,%2,%3}, {%4,%5,%6,%7}, {%8,%9}, {%0,%1,%2,%3};"
        : "+f"(d[0]), "+f"(d[1]), "+f"(d[2]), "+f"(d[3])
        : "r"(a[0]), "r"(a[1]), "r"(a[2]), "r"(a[3]), "r"(b[0]), "r"(b[1]));
}

// ---------------------------------------------------------------------------
// bf16x3 split GEMM via mma.sync (near-fp32 accuracy):
//   C[m,n] = alpha * sum_k A[m,k] * B(n,k)  (+bias +posenc)
//   BNK=true : B stored [N,K] row-major
//   BNK=false: B stored [K,N] row-major
// Tile 128x128x32, 256 threads (8 warps, 2x4), warp tile 64x32.
// SMEM fp32 (cp.async 2-stage); split to bf16 hi/lo in registers.
// ---------------------------------------------------------------------------
#define A_STRIDE 36      // floats per A smem row (32 + 4 pad)
#define BN_STRIDE 36     // floats per B smem row, BNK variant ([n][k])
#define BK_STRIDE 132    // floats per B smem row, !BNK variant ([k][n])
#define A_TILE_FLOATS  (128 * A_STRIDE)   // 4608
#define B_TILE_FLOATS  (128 * BN_STRIDE)  // 4608 (>= 32*132=4224)
#define STAGE_FLOATS   (A_TILE_FLOATS + B_TILE_FLOATS)  // 9216
#define DYN_SMEM       (2 * STAGE_FLOATS * 4)           // 73728 bytes

template <bool BNK>
__global__ __launch_bounds__(256, 2)
void tc_gemm(const float* __restrict__ A, const float* __restrict__ B,
             float* __restrict__ C, int M, int N, int K,
             long long sA, long long sB, long long sC,
             float alpha, const float* __restrict__ bias,
             const float* __restrict__ posenc)
{
    extern __shared__ float smem[];

    const int tid  = threadIdx.x;
    const int wid  = tid >> 5;
    const int lane = tid & 31;
    const int wm   = wid >> 2;       // 0..1 (M)
    const int wn   = wid & 3;        // 0..3 (N)
    const int g    = lane >> 2;      // groupID 0..7
    const int t    = lane & 3;       // threadID_in_group

    const int bz = blockIdx.z;
    A += bz * sA; B += bz * sB; C += bz * sC;
    const int m0 = blockIdx.y * 128;
    const int n0 = blockIdx.x * 128;

    const uint32_t smem_base = smem_u32(smem);

    float acc[4][4][4];
#pragma unroll
    for (int mi = 0; mi < 4; mi++)
#pragma unroll
        for (int ni = 0; ni < 4; ni++)
#pragma unroll
            for (int c = 0; c < 4; c++) acc[mi][ni][c] = 0.0f;

    const int NC = K >> 5;   // k-chunks of 32

    // ---- async stage loader ----
    auto issue_stage = [&](int c) {
        const int buf = c & 1;
        const int k0  = c * 32;
        const uint32_t as = smem_base + (buf * STAGE_FLOATS) * 4;
        const uint32_t bs = as + A_TILE_FLOATS * 4;
        // A tile: 128 rows x 32 floats = 1024 float4
#pragma unroll
        for (int i = 0; i < 4; i++) {
            const int e   = tid + i * 256;
            const int row = e >> 3;
            const int q   = e & 7;
            cp_async16(as + (row * A_STRIDE + q * 4) * 4,
                       A + (long long)(m0 + row) * K + k0 + q * 4);
        }
        if (BNK) {
            // B tile: [n][k] 128 rows x 32 floats
#pragma unroll
            for (int i = 0; i < 4; i++) {
                const int e   = tid + i * 256;
                const int row = e >> 3;
                const int q   = e & 7;
                cp_async16(bs + (row * BN_STRIDE + q * 4) * 4,
                           B + (long long)(n0 + row) * K + k0 + q * 4);
            }
        } else {
            // B tile: [k][n] 32 rows x 128 floats
#pragma unroll
            for (int i = 0; i < 4; i++) {
                const int e   = tid + i * 256;
                const int row = e >> 5;
                const int q   = e & 31;
                cp_async16(bs + (row * BK_STRIDE + q * 4) * 4,
                           B + (long long)(k0 + row) * N + n0 + q * 4);
            }
        }
        CP_COMMIT();
    };

    issue_stage(0);
    issue_stage(1);

    for (int c = 0; c < NC; ++c) {
        CP_WAIT1();
        __syncthreads();

        const int buf = c & 1;
        const float* As = smem + buf * STAGE_FLOATS;
        const float* Bs = As + A_TILE_FLOATS;

        // two k16 halves per 32-chunk
#pragma unroll
        for (int half = 0; half < 2; half++) {
            const int kk = half * 16;

            // ---- B fragments (hi/lo) ----
            uint32_t bh[4][2], bl[4][2];
#pragma unroll
            for (int ni = 0; ni < 4; ni++) {
                const int n = wn * 32 + ni * 8 + g;
                float p0x, p0y, p1x, p1y;
                if (BNK) {
                    const float* b = Bs + n * BN_STRIDE + kk;
                    float2 u = *(const float2*)(b + 2 * t);
                    float2 v = *(const float2*)(b + 8 + 2 * t);
                    p0x = u.x; p0y = u.y; p1x = v.x; p1y = v.y;
                } else {
                    const float* b = Bs + (kk + 2 * t) * BK_STRIDE + n;
                    p0x = b[0];
                    p0y = b[BK_STRIDE];
                    p1x = b[8 * BK_STRIDE];
                    p1y = b[9 * BK_STRIDE];
                }
                split_pack(p0x, p0y, bh[ni][0], bl[ni][0]);
                split_pack(p1x, p1y, bh[ni][1], bl[ni][1]);
            }

            // ---- A fragments per mi, then 3-term MMAs ----
#pragma unroll
            for (int mi = 0; mi < 4; mi++) {
                const float* a_lo = As + (wm * 64 + mi * 16 + g) * A_STRIDE + kk;
                const float* a_hi = a_lo + 8 * A_STRIDE;
                float2 q00 = *(const float2*)(a_lo + 2 * t);
                float2 q10 = *(const float2*)(a_hi + 2 * t);
                float2 q01 = *(const float2*)(a_lo + 8 + 2 * t);
                float2 q11 = *(const float2*)(a_hi + 8 + 2 * t);

                uint32_t ah[4], al[4];
                split_pack(q00.x, q00.y, ah[0], al[0]);
                split_pack(q10.x, q10.y, ah[1], al[1]);
                split_pack(q01.x, q01.y, ah[2], al[2]);
                split_pack(q11.x, q11.y, ah[3], al[3]);

#pragma unroll
                for (int ni = 0; ni < 4; ni++) {
                    mma_bf16(acc[mi][ni], ah, bh[ni]);
                    mma_bf16(acc[mi][ni], ah, bl[ni]);
                    mma_bf16(acc[mi][ni], al, bh[ni]);
                }
            }
        }

        __syncthreads();
        if (c + 2 < NC) issue_stage(c + 2);
        else            CP_COMMIT();   // keep group accounting uniform
    }

    // ---- epilogue ----
#pragma unroll
    for (int mi = 0; mi < 4; mi++) {
        const int m_lo = m0 + wm * 64 + mi * 16 + g;
        const int m_hi = m_lo + 8;
        const float* pe_lo = posenc ? posenc + (long long)(m_lo & (SEQL - 1)) * N : 0;
        const float* pe_hi = posenc ? posenc + (long long)(m_hi & (SEQL - 1)) * N : 0;
        float* c_lo = C + (long long)m_lo * N;
        float* c_hi = C + (long long)m_hi * N;
#pragma unroll
        for (int ni = 0; ni < 4; ni++) {
            const int n = n0 + wn * 32 + ni * 8 + 2 * t;
            float2 v0, v1;
            v0.x = acc[mi][ni][0] * alpha;
            v0.y = acc[mi][ni][1] * alpha;
            v1.x = acc[mi][ni][2] * alpha;
            v1.y = acc[mi][ni][3] * alpha;
            if (bias) {
                const float b0 = bias[n], b1 = bias[n + 1];
                v0.x += b0; v0.y += b1;
                v1.x += b0; v1.y += b1;
            }
            if (posenc) {
                v0.x += pe_lo[n]; v0.y += pe_lo[n + 1];
                v1.x += pe_hi[n]; v1.y += pe_hi[n + 1];
            }
            *(float2*)(c_lo + n) = v0;
            *(float2*)(c_hi + n) = v1;
        }
    }
}

// ---------------------------------------------------------------------------
// Row softmax, in place. Row length 2048, blockDim 256.
// ---------------------------------------------------------------------------
__global__ void softmax_rows(float* __restrict__ S)
{
    float* row = S + (long long)blockIdx.x * 2048;
    const int tid = threadIdx.x;
    __shared__ float red[256];

    float v[8];
    float mx = -1e30f;
#pragma unroll
    for (int i = 0; i < 8; i++) {
        v[i] = row[tid + i * 256];
        mx = fmaxf(mx, v[i]);
    }
    red[tid] = mx; __syncthreads();
    for (int s = 128; s > 0; s >>= 1) {
        if (tid < s) red[tid] = fmaxf(red[tid], red[tid + s]);
        __syncthreads();
    }
    mx = red[0]; __syncthreads();

    float sum = 0.0f;
#pragma unroll
    for (int i = 0; i < 8; i++) {
        v[i] = __expf(v[i] - mx);
        sum += v[i];
    }
    red[tid] = sum; __syncthreads();
    for (int s = 128; s > 0; s >>= 1) {
        if (tid < s) red[tid] += red[tid + s];
        __syncthreads();
    }
    const float inv = 1.0f / red[0];
#pragma unroll
    for (int i = 0; i < 8; i++)
        row[tid + i * 256] = v[i] * inv;
}

// ---------------------------------------------------------------------------
// h = x + z ; H = LayerNorm(h) * g + b
// ---------------------------------------------------------------------------
__global__ void add_ln_kernel(const float* __restrict__ X, const float* __restrict__ Z,
                              const float* __restrict__ g, const float* __restrict__ b,
                              float* __restrict__ H)
{
    const long long r = blockIdx.x;
    const int tid = threadIdx.x;
    const float* xr = X + r * DMODEL;
    const float* zr = Z + r * DMODEL;
    __shared__ float red[256];

    float h[4];
    float sum = 0.0f;
#pragma unroll
    for (int i = 0; i < 4; i++) {
        h[i] = xr[tid + i * 256] + zr[tid + i * 256];
        sum += h[i];
    }
    red[tid] = sum; __syncthreads();
    for (int s = 128; s > 0; s >>= 1) {
        if (tid < s) red[tid] += red[tid + s];
        __syncthreads();
    }
    const float mean = red[0] * (1.0f / DMODEL);
    __syncthreads();

    float vs = 0.0f;
#pragma unroll
    for (int i = 0; i < 4; i++) {
        const float d = h[i] - mean;
        vs += d * d;
    }
    red[tid] = vs; __syncthreads();
    for (int s = 128; s > 0; s >>= 1) {
        if (tid < s) red[tid] += red[tid + s];
        __syncthreads();
    }
    const float inv = rsqrtf(red[0] * (1.0f / DMODEL) + LN_EPS);

    float* Hr = H + r * DMODEL;
#pragma unroll
    for (int i = 0; i < 4; i++) {
        const int c = tid + i * 256;
        Hr[c] = (h[i] - mean) * inv * g[c] + b[c];
    }
}

// ---------------------------------------------------------------------------
// t[r] = sum_o tanh(SK[r,o]) * q[o]
// ---------------------------------------------------------------------------
__global__ void softkey_reduce(const float* __restrict__ SK, const float* __restrict__ q,
                               float* __restrict__ t)
{
    const long long r = blockIdx.x;
    const int tid = threadIdx.x;
    __shared__ float red[256];

    float s = 0.0f;
#pragma unroll
    for (int i = 0; i < 4; i++) {
        const int c = tid + i * 256;
        s += tanhf(SK[r * DMODEL + c]) * q[c];
    }
    red[tid] = s; __syncthreads();
    for (int k = 128; k > 0; k >>= 1) {
        if (tid < k) red[tid] += red[tid + k];
        __syncthreads();
    }
    if (tid == 0) t[r] = red[0];
}

// ---------------------------------------------------------------------------
// out[b,o] = sum_s w[b,s] * H[b,s,o]
// ---------------------------------------------------------------------------
__global__ void final_out(const float* __restrict__ H, const float* __restrict__ w,
                          float* __restrict__ out)
{
    const int b = blockIdx.y;
    const int o = blockIdx.x * 256 + threadIdx.x;
    const float* Hb = H + (long long)b * SEQL * DMODEL;
    const float* wb = w + (long long)b * SEQL;

    float a0 = 0.0f, a1 = 0.0f, a2 = 0.0f, a3 = 0.0f;
    for (int s = 0; s < SEQL; s += 4) {
        a0 += wb[s + 0] * Hb[(long long)(s + 0) * DMODEL + o];
        a1 += wb[s + 1] * Hb[(long long)(s + 1) * DMODEL + o];
        a2 += wb[s + 2] * Hb[(long long)(s + 2) * DMODEL + o];
        a3 += wb[s + 3] * Hb[(long long)(s + 3) * DMODEL + o];
    }
    out[b * DMODEL + o] = (a0 + a1) + (a2 + a3);
}

// ---------------------------------------------------------------------------
// Launch
// ---------------------------------------------------------------------------
extern "C" void kernel_launch(void* const* d_in, const int* in_sizes, int n_in,
                              void* d_out, int out_size)
{
    const float* inputs  = (const float*)d_in[0];
    const float* embed_w = (const float*)d_in[1];
    const float* embed_b = (const float*)d_in[2];
    const float* wq_w    = (const float*)d_in[3];
    const float* wq_b    = (const float*)d_in[4];
    const float* wk_w    = (const float*)d_in[5];
    const float* wk_b    = (const float*)d_in[6];
    const float* wv_w    = (const float*)d_in[7];
    const float* wv_b    = (const float*)d_in[8];
    const float* ln_g    = (const float*)d_in[9];
    const float* ln_b    = (const float*)d_in[10];
    const float* skw     = (const float*)d_in[11];
    const float* sq      = (const float*)d_in[12];
    const float* pos     = (const float*)d_in[13];
    float* out = (float*)d_out;

    cudaFuncSetAttribute((const void*)tc_gemm<true>,
                         cudaFuncAttributeMaxDynamicSharedMemorySize, DYN_SMEM);
    cudaFuncSetAttribute((const void*)tc_gemm<false>,
                         cudaFuncAttributeMaxDynamicSharedMemorySize, DYN_SMEM);

    float* base = 0;
    cudaGetSymbolAddress((void**)&base, g_scratch);
    float* X  = base + O_X;
    float* Q  = base + O_Q;
    float* K  = base + O_K;
    float* V  = base + O_V;
    float* Z  = base + O_Z;
    float* H  = base + O_H;
    float* SK = base + O_SK;
    float* SC = base + O_SCORE;
    float* T  = base + O_T;

    // 1) embed: X = inputs @ embed_w^T + embed_b + pos_enc
    tc_gemm<true><<<dim3(DMODEL / 128, NROW / 128, 1), 256, DYN_SMEM>>>(
        inputs, embed_w, X, NROW, DMODEL, D_IN, 0, 0, 0, 1.0f, embed_b, pos);

    // 2) Q, K, V
    tc_gemm<true><<<dim3(DMODEL / 128, NROW / 128, 1), 256, DYN_SMEM>>>(
        X, wq_w, Q, NROW, DMODEL, DMODEL, 0, 0, 0, 1.0f, wq_b, 0);
    tc_gemm<true><<<dim3(DMODEL / 128, NROW / 128, 1), 256, DYN_SMEM>>>(
        X, wk_w, K, NROW, DMODEL, DMODEL, 0, 0, 0, 1.0f, wk_b, 0);
    tc_gemm<true><<<dim3(DMODEL / 128, NROW / 128, 1), 256, DYN_SMEM>>>(
        X, wv_w, V, NROW, DMODEL, DMODEL, 0, 0, 0, 1.0f, wv_b, 0);

    // 3) scores = Q @ K^T / 32   (batched over 8)
    tc_gemm<true><<<dim3(SEQL / 128, SEQL / 128, BATCH), 256, DYN_SMEM>>>(
        Q, K, SC, SEQL, SEQL, DMODEL,
        (long long)SEQL * DMODEL, (long long)SEQL * DMODEL, (long long)SEQL * SEQL,
        1.0f / 32.0f, 0, 0);

    // 4) softmax over rows
    softmax_rows<<<NROW, 256>>>(SC);

    // 5) Z = score @ V    (batched, B is [K,N])
    tc_gemm<false><<<dim3(DMODEL / 128, SEQL / 128, BATCH), 256, DYN_SMEM>>>(
        SC, V, Z, SEQL, DMODEL, SEQL,
        (long long)SEQL * SEQL, (long long)SEQL * DMODEL, (long long)SEQL * DMODEL,
        1.0f, 0, 0);

    // 6) H = LN(X + Z) * g + b
    add_ln_kernel<<<NROW, 256>>>(X, Z, ln_g, ln_b, H);

    // 7) SK = H @ soft_key_w^T
    tc_gemm<true><<<dim3(DMODEL / 128, NROW / 128, 1), 256, DYN_SMEM>>>(
        H, skw, SK, NROW, DMODEL, DMODEL, 0, 0, 0, 1.0f, 0, 0);

    // 8) t[b,s] = sum_o tanh(SK) * soft_query[o]; softmax over s per batch
    softkey_reduce<<<NROW, 256>>>(SK, sq, T);
    softmax_rows<<<BATCH, 256>>>(T);

    // 9) out[b,o] = sum_s w[b,s] * H[b,s,o]
    final_out<<<dim3(DMODEL / 256, BATCH), 256>>>(H, T, out);
}